// round 1
// baseline (speedup 1.0000x reference)
#include <cuda_runtime.h>
#include <cstdint>
#include <cstdio>

#define DEVFN __device__ __forceinline__

// ---------------- packed f32x2 helpers (sm_100+ PTX) ----------------
DEVFN unsigned long long pack2(float lo, float hi) {
    unsigned long long r;
    asm("mov.b64 %0, {%1,%2};" : "=l"(r) : "f"(lo), "f"(hi));
    return r;
}
DEVFN void unpack2(unsigned long long v, float& lo, float& hi) {
    asm("mov.b64 {%0,%1}, %2;" : "=f"(lo), "=f"(hi) : "l"(v));
}
DEVFN void fma2(unsigned long long& d, unsigned long long a, unsigned long long b) {
    asm("fma.rn.f32x2 %0, %1, %2, %0;" : "+l"(d) : "l"(a), "l"(b));
}
DEVFN float sigf(float x) { return __fdividef(1.f, 1.f + __expf(-x)); }
DEVFN float reluf(float x) { return fmaxf(x, 0.f); }

static constexpr int BATCH = 8192;
static constexpr int TT    = 30;

// ---------------- scratch (static __device__ — no allocation) ----------------
__device__ float g_bufA[(size_t)BATCH * TT * 512];   // L1 out (w=128), L3 out (w=512)
__device__ float g_bufB[(size_t)BATCH * TT * 256];   // L2 out (w=256)
__device__ float g_h1[(size_t)BATCH * 256];          // dense1 out
__device__ __align__(128) float g_wl1[2ull * 190 * 64 * 8];
__device__ __align__(128) float g_wl2[2ull * 256 * 128 * 8];
__device__ __align__(128) float g_wl3[2ull * 512 * 256 * 8];
__device__ __align__(128) float g_wd1[2ull * 15360 * 256];

// ---------------- weight prep ----------------
// dst[((k*U + j)*4 + g)*2 + {0,1}] = concat(W,Uw)[k][g*U + j]  (duplicated pair)
__global__ void pack_lstm_w(const float* __restrict__ W, const float* __restrict__ Uw,
                            float* __restrict__ dst, int DIN, int U) {
    int total = (DIN + U) * U * 4;
    for (int idx = blockIdx.x * blockDim.x + threadIdx.x; idx < total;
         idx += gridDim.x * blockDim.x) {
        int g = idx & 3;
        int rest = idx >> 2;
        int j = rest % U;
        int k = rest / U;
        float w = (k < DIN) ? W[(size_t)k * 4 * U + g * U + j]
                            : Uw[(size_t)(k - DIN) * 4 * U + g * U + j];
        dst[2 * (size_t)idx]     = w;
        dst[2 * (size_t)idx + 1] = w;
    }
}

__global__ void pack_dup(const float* __restrict__ src, float* __restrict__ dst, int n) {
    for (int idx = blockIdx.x * blockDim.x + threadIdx.x; idx < n;
         idx += gridDim.x * blockDim.x) {
        float v = src[idx];
        dst[2 * (size_t)idx]     = v;
        dst[2 * (size_t)idx + 1] = v;
    }
}

// ---------------- fused BiLSTM layer ----------------
// One block = 64 batch rows x one direction, persistent over all 30 timesteps.
// Per step: z = [x_t | h] @ [W;U] + b ; gates ; h,c update. No global sync needed.
template <int DIN, int U, int THREADS>
__global__ void __launch_bounds__(THREADS) lstm_kernel(
    const float* __restrict__ in,    // [B][T][DIN]
    float* __restrict__ out,         // [B][T][2U]
    const float* __restrict__ Wdup,  // [2][(DIN+U)*U*8]
    const float* __restrict__ bias_f,
    const float* __restrict__ bias_b) {
    constexpr int K      = DIN + U;
    constexpr int ROWS   = 64;
    constexpr int RP     = ROWS + 2;           // pad: conflict-free + keeps 8B align
    constexpr int NU     = 32;                 // units per chunk (lane -> unit)
    constexpr int CHUNKS = U / NU;
    constexpr int CELLS  = (ROWS * NU) / THREADS;  // rows per thread per chunk
    constexpr int PAIRS  = CELLS / 2;
    constexpr int CP     = CHUNKS * PAIRS;     // packed c-state per thread

    extern __shared__ float smem[];
    float* x_s = smem;                 // [DIN][RP]  (k-major)
    float* h_s = smem + DIN * RP;      // [2][U][RP] (k-major, ping-pong)

    const int tid  = threadIdx.x;
    const int lane = tid & 31;
    const int warp = tid >> 5;
    const int dir  = blockIdx.y;
    const int b0   = blockIdx.x * ROWS;
    const int rb   = warp * CELLS;

    const float* Wd   = Wdup + (size_t)dir * (size_t)K * U * 8;
    const float* bias = dir ? bias_b : bias_f;

    unsigned long long c2[CP];
#pragma unroll
    for (int i = 0; i < CP; i++) c2[i] = 0ull;

    for (int i = tid; i < 2 * U * RP; i += THREADS) h_s[i] = 0.f;

    int cur = 0;
    for (int step = 0; step < TT; ++step) {
        const int t = dir ? (TT - 1 - step) : step;
        __syncthreads();
        // stage x_t transposed into smem (k-major so row-pairs are one LDS.64)
        const float* xin = in + ((size_t)b0 * TT + t) * DIN;
        for (int i = tid; i < ROWS * DIN; i += THREADS) {
            int r = i / DIN, k = i - r * DIN;
            x_s[k * RP + r] = xin[(size_t)r * TT * DIN + k];
        }
        __syncthreads();

        float*       hn = h_s + (cur ^ 1) * U * RP;
        const float* hc = h_s + cur * U * RP;

#pragma unroll 1
        for (int ch = 0; ch < CHUNKS; ++ch) {
            const int j = ch * NU + lane;
            unsigned long long ai[PAIRS], af[PAIRS], ag[PAIRS], ao[PAIRS];
            {
                float bi = bias[j], bf = bias[U + j], bg = bias[2 * U + j], bo = bias[3 * U + j];
                unsigned long long pi = pack2(bi, bi), pf = pack2(bf, bf);
                unsigned long long pg = pack2(bg, bg), po = pack2(bo, bo);
#pragma unroll
                for (int p = 0; p < PAIRS; p++) { ai[p] = pi; af[p] = pf; ag[p] = pg; ao[p] = po; }
            }
            const ulonglong2* wp = reinterpret_cast<const ulonglong2*>(Wd + (size_t)j * 8);
            // ---- x part ----
#pragma unroll 4
            for (int k = 0; k < DIN; ++k) {
                ulonglong2 wif = wp[0];   // {wi,wi},{wf,wf}
                ulonglong2 wgo = wp[1];   // {wg,wg},{wo,wo}
                wp += U * 2;
#pragma unroll
                for (int p = 0; p < PAIRS; p++) {
                    unsigned long long a2 =
                        *reinterpret_cast<const unsigned long long*>(&x_s[k * RP + rb + 2 * p]);
                    fma2(ai[p], a2, wif.x); fma2(af[p], a2, wif.y);
                    fma2(ag[p], a2, wgo.x); fma2(ao[p], a2, wgo.y);
                }
            }
            // ---- h part ----
#pragma unroll 4
            for (int k = 0; k < U; ++k) {
                ulonglong2 wif = wp[0];
                ulonglong2 wgo = wp[1];
                wp += U * 2;
#pragma unroll
                for (int p = 0; p < PAIRS; p++) {
                    unsigned long long a2 =
                        *reinterpret_cast<const unsigned long long*>(&hc[k * RP + rb + 2 * p]);
                    fma2(ai[p], a2, wif.x); fma2(af[p], a2, wif.y);
                    fma2(ag[p], a2, wgo.x); fma2(ao[p], a2, wgo.y);
                }
            }
            // ---- gates + state update ----
#pragma unroll
            for (int p = 0; p < PAIRS; p++) {
                float i0, i1, f0, f1, gg0, gg1, o0, o1, co0, co1;
                unpack2(ai[p], i0, i1);
                unpack2(af[p], f0, f1);
                unpack2(ag[p], gg0, gg1);
                unpack2(ao[p], o0, o1);
                unpack2(c2[ch * PAIRS + p], co0, co1);
                float cn0 = sigf(f0) * co0 + sigf(i0) * reluf(gg0);
                float cn1 = sigf(f1) * co1 + sigf(i1) * reluf(gg1);
                float h0  = sigf(o0) * reluf(cn0);
                float h1  = sigf(o1) * reluf(cn1);
                c2[ch * PAIRS + p] = pack2(cn0, cn1);
                int r0 = rb + 2 * p;
                *reinterpret_cast<unsigned long long*>(&hn[j * RP + r0]) = pack2(h0, h1);
                size_t ob = ((size_t)(b0 + r0) * TT + t) * (2 * U) + (size_t)dir * U + j;
                out[ob]                         = h0;
                out[ob + (size_t)TT * 2 * U]    = h1;   // row r0+1
            }
        }
        cur ^= 1;
    }
}

// ---------------- dense1: [8192,15360]@[15360,256]+b, relu ----------------
__global__ void __launch_bounds__(256) dense1_kernel(
    const float* __restrict__ A,     // [B][15360]
    const float* __restrict__ Wdup,  // [15360*256*2] duplicated pairs
    const float* __restrict__ bias,  // [256]
    float* __restrict__ Out) {       // [B][256]
    constexpr int BM = 64, KT = 32, KDIM = 15360, NDIM = 256;
    __shared__ float a_s[KT][BM + 2];
    int tid = threadIdx.x, tx = tid & 15, ty = tid >> 4;
    int r0 = blockIdx.x * BM, n0 = blockIdx.y * 64;
    int n  = n0 + tx * 4;
    int rb = ty * 4;
    unsigned long long acc[2][4];
#pragma unroll
    for (int p = 0; p < 2; p++)
#pragma unroll
        for (int c = 0; c < 4; c++) acc[p][c] = 0ull;

    for (int kt = 0; kt < KDIM; kt += KT) {
        __syncthreads();
        for (int i = tid; i < BM * KT; i += 256) {
            int r = i >> 5, k = i & 31;
            a_s[k][r] = A[(size_t)(r0 + r) * KDIM + kt + k];
        }
        __syncthreads();
#pragma unroll 8
        for (int k = 0; k < KT; k++) {
            const ulonglong2* wp = reinterpret_cast<const ulonglong2*>(
                Wdup + ((size_t)(kt + k) * NDIM + n) * 2);
            ulonglong2 w01 = wp[0], w23 = wp[1];
#pragma unroll
            for (int p = 0; p < 2; p++) {
                unsigned long long a2 =
                    *reinterpret_cast<const unsigned long long*>(&a_s[k][rb + 2 * p]);
                fma2(acc[p][0], a2, w01.x);
                fma2(acc[p][1], a2, w01.y);
                fma2(acc[p][2], a2, w23.x);
                fma2(acc[p][3], a2, w23.y);
            }
        }
    }
    float bv[4] = {bias[n], bias[n + 1], bias[n + 2], bias[n + 3]};
#pragma unroll
    for (int p = 0; p < 2; p++) {
        float lo[4], hi[4];
#pragma unroll
        for (int c = 0; c < 4; c++) unpack2(acc[p][c], lo[c], hi[c]);
        int r = r0 + rb + 2 * p;
        float4 v0 = {reluf(lo[0] + bv[0]), reluf(lo[1] + bv[1]), reluf(lo[2] + bv[2]), reluf(lo[3] + bv[3])};
        float4 v1 = {reluf(hi[0] + bv[0]), reluf(hi[1] + bv[1]), reluf(hi[2] + bv[2]), reluf(hi[3] + bv[3])};
        *reinterpret_cast<float4*>(&Out[(size_t)r * 256 + n])       = v0;
        *reinterpret_cast<float4*>(&Out[(size_t)(r + 1) * 256 + n]) = v1;
    }
}

// ---------------- tail: d2+relu, d3+relu, BN, out, softmax ----------------
__global__ void __launch_bounds__(128) tail_kernel(
    const float* __restrict__ H1,
    const float* __restrict__ W2, const float* __restrict__ B2,
    const float* __restrict__ W3, const float* __restrict__ B3,
    const float* __restrict__ G, const float* __restrict__ Bb,
    const float* __restrict__ M, const float* __restrict__ V,
    const float* __restrict__ WO, const float* __restrict__ BO,
    float* __restrict__ Out) {
    __shared__ float h1s[4][256];
    __shared__ float h2s[4][128];
    __shared__ float h3s[4][64];
    int tid = threadIdx.x, lane = tid & 31, w = tid >> 5;
    int r0 = blockIdx.x * 4;
    for (int i = tid; i < 4 * 256; i += 128) h1s[i >> 8][i & 255] = H1[(size_t)r0 * 256 + i];
    __syncthreads();

    // d2: row r0+w, lane covers cols lane*4..+3
    {
        int j = lane * 4;
        float4 bv = *reinterpret_cast<const float4*>(&B2[j]);
        float a0 = bv.x, a1 = bv.y, a2 = bv.z, a3 = bv.w;
#pragma unroll 4
        for (int k = 0; k < 256; k++) {
            float a = h1s[w][k];
            float4 wv = *reinterpret_cast<const float4*>(&W2[(size_t)k * 128 + j]);
            a0 += a * wv.x; a1 += a * wv.y; a2 += a * wv.z; a3 += a * wv.w;
        }
        h2s[w][j]     = reluf(a0);
        h2s[w][j + 1] = reluf(a1);
        h2s[w][j + 2] = reluf(a2);
        h2s[w][j + 3] = reluf(a3);
    }
    __syncwarp();
    // d3 + BN
    {
        int j = lane * 2;
        float a0 = B3[j], a1 = B3[j + 1];
#pragma unroll 4
        for (int k = 0; k < 128; k++) {
            float a = h2s[w][k];
            float2 wv = *reinterpret_cast<const float2*>(&W3[(size_t)k * 64 + j]);
            a0 += a * wv.x; a1 += a * wv.y;
        }
        a0 = reluf(a0); a1 = reluf(a1);
        float s0 = rsqrtf(V[j] + 1e-3f)     * G[j];
        float s1 = rsqrtf(V[j + 1] + 1e-3f) * G[j + 1];
        h3s[w][j]     = (a0 - M[j])     * s0 + Bb[j];
        h3s[w][j + 1] = (a1 - M[j + 1]) * s1 + Bb[j + 1];
    }
    __syncwarp();
    // output logits + softmax (26 classes on lanes 0..25)
    float logit = -3.0e38f;
    if (lane < 26) {
        float a = BO[lane];
#pragma unroll 4
        for (int k = 0; k < 64; k++) a += h3s[w][k] * WO[(size_t)k * 26 + lane];
        logit = a;
    }
    float mx = logit;
#pragma unroll
    for (int o = 16; o; o >>= 1) mx = fmaxf(mx, __shfl_xor_sync(0xffffffffu, mx, o));
    float e = (lane < 26) ? __expf(logit - mx) : 0.f;
    float s = e;
#pragma unroll
    for (int o = 16; o; o >>= 1) s += __shfl_xor_sync(0xffffffffu, s, o);
    if (lane < 26) Out[(size_t)(r0 + w) * 26 + lane] = e * __fdividef(1.f, s);
}

// ---------------- launch ----------------
extern "C" void kernel_launch(void* const* d_in, const int* in_sizes, int n_in,
                              void* d_out, int out_size) {
    const float* x   = (const float*)d_in[0];
    const float* w1f = (const float*)d_in[1];
    const float* u1f = (const float*)d_in[2];
    const float* b1f = (const float*)d_in[3];
    const float* w1b = (const float*)d_in[4];
    const float* u1b = (const float*)d_in[5];
    const float* b1b = (const float*)d_in[6];
    const float* w2f = (const float*)d_in[7];
    const float* u2f = (const float*)d_in[8];
    const float* b2f = (const float*)d_in[9];
    const float* w2b = (const float*)d_in[10];
    const float* u2b = (const float*)d_in[11];
    const float* b2b = (const float*)d_in[12];
    const float* w3f = (const float*)d_in[13];
    const float* u3f = (const float*)d_in[14];
    const float* b3f = (const float*)d_in[15];
    const float* w3b = (const float*)d_in[16];
    const float* u3b = (const float*)d_in[17];
    const float* b3b = (const float*)d_in[18];
    const float* d1w = (const float*)d_in[19];
    const float* d1b = (const float*)d_in[20];
    const float* d2w = (const float*)d_in[21];
    const float* d2b = (const float*)d_in[22];
    const float* d3w = (const float*)d_in[23];
    const float* d3b = (const float*)d_in[24];
    const float* bng = (const float*)d_in[25];
    const float* bnb = (const float*)d_in[26];
    const float* bnm = (const float*)d_in[27];
    const float* bnv = (const float*)d_in[28];
    const float* ow  = (const float*)d_in[29];
    const float* ob  = (const float*)d_in[30];

    float *bufA, *bufB, *h1, *wl1, *wl2, *wl3, *wd1;
    cudaGetSymbolAddress((void**)&bufA, g_bufA);
    cudaGetSymbolAddress((void**)&bufB, g_bufB);
    cudaGetSymbolAddress((void**)&h1, g_h1);
    cudaGetSymbolAddress((void**)&wl1, g_wl1);
    cudaGetSymbolAddress((void**)&wl2, g_wl2);
    cudaGetSymbolAddress((void**)&wl3, g_wl3);
    cudaGetSymbolAddress((void**)&wd1, g_wd1);

    const size_t s1 = (126 * 66 + 2 * 64 * 66) * sizeof(float);   // ~67 KB
    const size_t s2 = (128 * 66 + 2 * 128 * 66) * sizeof(float);  // ~101 KB
    const size_t s3 = (256 * 66 + 2 * 256 * 66) * sizeof(float);  // ~203 KB
    cudaFuncSetAttribute(lstm_kernel<126, 64, 256>,
                         cudaFuncAttributeMaxDynamicSharedMemorySize, (int)s1);
    cudaFuncSetAttribute(lstm_kernel<128, 128, 256>,
                         cudaFuncAttributeMaxDynamicSharedMemorySize, (int)s2);
    cudaFuncSetAttribute(lstm_kernel<256, 256, 512>,
                         cudaFuncAttributeMaxDynamicSharedMemorySize, (int)s3);

    // weight prep (cheap; inside the graph, deterministic)
    pack_lstm_w<<<256, 256>>>(w1f, u1f, wl1, 126, 64);
    pack_lstm_w<<<256, 256>>>(w1b, u1b, wl1 + (size_t)190 * 64 * 8, 126, 64);
    pack_lstm_w<<<512, 256>>>(w2f, u2f, wl2, 128, 128);
    pack_lstm_w<<<512, 256>>>(w2b, u2b, wl2 + (size_t)256 * 128 * 8, 128, 128);
    pack_lstm_w<<<1024, 256>>>(w3f, u3f, wl3, 256, 256);
    pack_lstm_w<<<1024, 256>>>(w3b, u3b, wl3 + (size_t)512 * 256 * 8, 256, 256);
    pack_dup<<<2048, 256>>>(d1w, wd1, 15360 * 256);

    lstm_kernel<126, 64, 256><<<dim3(BATCH / 64, 2), 256, s1>>>(x, bufA, wl1, b1f, b1b);
    lstm_kernel<128, 128, 256><<<dim3(BATCH / 64, 2), 256, s2>>>(bufA, bufB, wl2, b2f, b2b);
    lstm_kernel<256, 256, 512><<<dim3(BATCH / 64, 2), 512, s3>>>(bufB, bufA, wl3, b3f, b3b);

    dense1_kernel<<<dim3(BATCH / 64, 4), 256>>>(bufA, wd1, d1b, h1);
    tail_kernel<<<BATCH / 4, 128>>>(h1, d2w, d2b, d3w, d3b, bng, bnb, bnm, bnv, ow, ob,
                                    (float*)d_out);
    (void)in_sizes; (void)n_in; (void)out_size;
}

// round 2
// speedup vs baseline: 2.1178x; 2.1178x over previous
#include <cuda_runtime.h>
#include <cstdint>

#define DEVFN __device__ __forceinline__

// ---------------- packed f32x2 helpers (sm_100+ PTX) ----------------
DEVFN unsigned long long pack2(float lo, float hi) {
    unsigned long long r;
    asm("mov.b64 %0, {%1,%2};" : "=l"(r) : "f"(lo), "f"(hi));
    return r;
}
DEVFN void unpack2(unsigned long long v, float& lo, float& hi) {
    asm("mov.b64 {%0,%1}, %2;" : "=f"(lo), "=f"(hi) : "l"(v));
}
DEVFN void fma2(unsigned long long& d, unsigned long long a, unsigned long long b) {
    asm("fma.rn.f32x2 %0, %1, %2, %0;" : "+l"(d) : "l"(a), "l"(b));
}
DEVFN float sigf(float x) { return __fdividef(1.f, 1.f + __expf(-x)); }
DEVFN float reluf(float x) { return fmaxf(x, 0.f); }

static constexpr int BATCH = 8192;
static constexpr int TT    = 30;

// ---------------- scratch (static __device__ — no allocation) ----------------
__device__ float g_bufA[(size_t)BATCH * TT * 512];   // L1 out (w=128), L3 out (w=512)
__device__ float g_bufB[(size_t)BATCH * TT * 256];   // L2 out (w=256)
__device__ float g_h1[(size_t)BATCH * 256];          // dense1 out
__device__ __align__(128) float g_wl1[2ull * 190 * 64 * 4];
__device__ __align__(128) float g_wl2[2ull * 256 * 128 * 4];
__device__ __align__(128) float g_wl3[2ull * 512 * 256 * 4];

// ---------------- weight prep ----------------
// Per dir: dst[(k*U + j)*4 + g] = concat(W,Uw)[k][g*U + j]
// -> float4 {wi,wf,wg,wo} per (k, unit j); lanes (consecutive j) are 16B apart: coalesced.
__global__ void pack_lstm_w(const float* __restrict__ Wf, const float* __restrict__ Uf,
                            const float* __restrict__ Wb, const float* __restrict__ Ub,
                            float* __restrict__ dst, int DIN, int U) {
    int half  = (DIN + U) * U * 4;
    int total = 2 * half;
    for (int idx = blockIdx.x * blockDim.x + threadIdx.x; idx < total;
         idx += gridDim.x * blockDim.x) {
        int d  = idx >= half;
        int id = idx - d * half;
        int g = id & 3;
        int rest = id >> 2;
        int j = rest % U;
        int k = rest / U;
        const float* W  = d ? Wb : Wf;
        const float* Uw = d ? Ub : Uf;
        float w = (k < DIN) ? W[(size_t)k * 4 * U + g * U + j]
                            : Uw[(size_t)(k - DIN) * 4 * U + g * U + j];
        dst[idx] = w;
    }
}

// ---------------- fused BiLSTM layer ----------------
// One block = 64 batch rows x one direction, persistent over all 30 timesteps.
// Warp owns (chunk-group of 32 units) x (16 rows). Weights: 1 coalesced LDG.128/k,
// duplicated to {w,w} in registers; activations: LDS.64 row-pair broadcasts.
template <int DIN, int U, int THREADS, int CPW>
__global__ void __launch_bounds__(THREADS) lstm_kernel(
    const float* __restrict__ in,    // [B][T][DIN]
    float* __restrict__ out,         // [B][T][2U]
    const float* __restrict__ Wp,    // [2][(DIN+U)*U*4] float4 layout
    const float* __restrict__ bias_f,
    const float* __restrict__ bias_b) {
    constexpr int K     = DIN + U;
    constexpr int ROWS  = 64;
    constexpr int RP    = ROWS + 2;
    constexpr int NCH   = U / 32;          // 32-unit chunks
    constexpr int NW    = THREADS / 32;
    constexpr int CHG   = NCH / CPW;       // chunk groups
    constexpr int RG    = NW / CHG;        // row groups
    constexpr int RPW   = ROWS / RG;       // rows per warp
    constexpr int PAIRS = RPW / 2;
    static_assert(RG * CHG == NW, "warp mapping");

    extern __shared__ float smem[];
    float* x_s = smem;                 // [DIN][RP]  (k-major)
    float* h_s = smem + DIN * RP;      // [2][U][RP] (k-major, ping-pong)

    const int tid  = threadIdx.x;
    const int lane = tid & 31;
    const int warp = tid >> 5;
    const int dir  = blockIdx.y;
    const int b0   = blockIdx.x * ROWS;
    const int chg  = warp % CHG;
    const int rb   = (warp / CHG) * RPW;

    const float* Wd   = Wp + (size_t)dir * K * U * 4;
    const float* bias = dir ? bias_b : bias_f;

    // hoist biases (constant across steps)
    float bi_r[CPW], bf_r[CPW], bg_r[CPW], bo_r[CPW];
#pragma unroll
    for (int cg = 0; cg < CPW; cg++) {
        int j = (chg * CPW + cg) * 32 + lane;
        bi_r[cg] = bias[j];
        bf_r[cg] = bias[U + j];
        bg_r[cg] = bias[2 * U + j];
        bo_r[cg] = bias[3 * U + j];
    }

    unsigned long long c2[CPW][PAIRS];
#pragma unroll
    for (int cg = 0; cg < CPW; cg++)
#pragma unroll
        for (int p = 0; p < PAIRS; p++) c2[cg][p] = 0ull;

    for (int i = tid; i < 2 * U * RP; i += THREADS) h_s[i] = 0.f;

    int cur = 0;
    for (int step = 0; step < TT; ++step) {
        const int t = dir ? (TT - 1 - step) : step;
        __syncthreads();
        // stage x_t transposed (k-major so row-pairs are one LDS.64 broadcast)
        const float* xin = in + ((size_t)b0 * TT + t) * DIN;
        for (int i = tid; i < ROWS * DIN; i += THREADS) {
            int r = i / DIN, k = i - r * DIN;
            x_s[k * RP + r] = xin[(size_t)r * TT * DIN + k];
        }
        __syncthreads();

        float*       hn = h_s + (cur ^ 1) * U * RP;
        const float* hc = h_s + cur * U * RP;

#pragma unroll 1
        for (int cg = 0; cg < CPW; ++cg) {
            const int j = (chg * CPW + cg) * 32 + lane;
            unsigned long long ai[PAIRS], af[PAIRS], ag[PAIRS], ao[PAIRS];
            {
                unsigned long long pi = pack2(bi_r[cg], bi_r[cg]);
                unsigned long long pf = pack2(bf_r[cg], bf_r[cg]);
                unsigned long long pg = pack2(bg_r[cg], bg_r[cg]);
                unsigned long long po = pack2(bo_r[cg], bo_r[cg]);
#pragma unroll
                for (int p = 0; p < PAIRS; p++) { ai[p] = pi; af[p] = pf; ag[p] = pg; ao[p] = po; }
            }
            const float* wrow = Wd + (size_t)j * 4;
            // ---- x part ----
#pragma unroll 2
            for (int k = 0; k < DIN; ++k) {
                float4 w = *reinterpret_cast<const float4*>(wrow);
                wrow += 4 * U;
                unsigned long long wi = pack2(w.x, w.x), wf = pack2(w.y, w.y);
                unsigned long long wg = pack2(w.z, w.z), wo = pack2(w.w, w.w);
                const float* src = &x_s[k * RP + rb];
#pragma unroll
                for (int p = 0; p < PAIRS; p++) {
                    unsigned long long a2 =
                        *reinterpret_cast<const unsigned long long*>(src + 2 * p);
                    fma2(ai[p], a2, wi); fma2(af[p], a2, wf);
                    fma2(ag[p], a2, wg); fma2(ao[p], a2, wo);
                }
            }
            // ---- h part ----
#pragma unroll 2
            for (int k = 0; k < U; ++k) {
                float4 w = *reinterpret_cast<const float4*>(wrow);
                wrow += 4 * U;
                unsigned long long wi = pack2(w.x, w.x), wf = pack2(w.y, w.y);
                unsigned long long wg = pack2(w.z, w.z), wo = pack2(w.w, w.w);
                const float* src = &hc[k * RP + rb];
#pragma unroll
                for (int p = 0; p < PAIRS; p++) {
                    unsigned long long a2 =
                        *reinterpret_cast<const unsigned long long*>(src + 2 * p);
                    fma2(ai[p], a2, wi); fma2(af[p], a2, wf);
                    fma2(ag[p], a2, wg); fma2(ao[p], a2, wo);
                }
            }
            // ---- gates + state update ----
#pragma unroll
            for (int p = 0; p < PAIRS; p++) {
                float i0, i1, f0, f1, gg0, gg1, o0, o1, co0, co1;
                unpack2(ai[p], i0, i1);
                unpack2(af[p], f0, f1);
                unpack2(ag[p], gg0, gg1);
                unpack2(ao[p], o0, o1);
                unpack2(c2[cg][p], co0, co1);
                float cn0 = sigf(f0) * co0 + sigf(i0) * reluf(gg0);
                float cn1 = sigf(f1) * co1 + sigf(i1) * reluf(gg1);
                float h0  = sigf(o0) * reluf(cn0);
                float h1  = sigf(o1) * reluf(cn1);
                c2[cg][p] = pack2(cn0, cn1);
                int r0 = rb + 2 * p;
                *reinterpret_cast<unsigned long long*>(&hn[j * RP + r0]) = pack2(h0, h1);
                size_t ob = ((size_t)(b0 + r0) * TT + t) * (2 * U) + (size_t)dir * U + j;
                out[ob]                      = h0;
                out[ob + (size_t)TT * 2 * U] = h1;
            }
        }
        cur ^= 1;
    }
}

// ---------------- dense1: [8192,15360]@[15360,256]+b, relu ----------------
// Warp = (128-col group) x (16 rows): 1 coalesced LDG.128 of natural-layout d1_w
// per k, reg-duplicated; 32 FFMA2 per load.
__global__ void __launch_bounds__(256) dense1_kernel(
    const float* __restrict__ A,     // [B][15360]
    const float* __restrict__ W,     // [15360][256] natural layout
    const float* __restrict__ bias,  // [256]
    float* __restrict__ Out) {       // [B][256]
    constexpr int BM = 64, KT = 32, KD = 15360;
    __shared__ float a_s[KT][BM + 2];
    const int tid = threadIdx.x, lane = tid & 31, warp = tid >> 5;
    const int ng = warp & 1, rg = warp >> 1;       // 2 col-groups x 4 row-groups
    const int n  = ng * 128 + lane * 4;
    const int rb = rg * 16;
    const int r0 = blockIdx.x * BM;

    unsigned long long acc[8][4];
#pragma unroll
    for (int p = 0; p < 8; p++)
#pragma unroll
        for (int c = 0; c < 4; c++) acc[p][c] = 0ull;

    for (int kt = 0; kt < KD; kt += KT) {
        __syncthreads();
        for (int i = tid; i < BM * KT; i += 256) {
            int r = i >> 5, k = i & 31;
            a_s[k][r] = A[(size_t)(r0 + r) * KD + kt + k];
        }
        __syncthreads();
#pragma unroll 2
        for (int k = 0; k < KT; k++) {
            float4 w = *reinterpret_cast<const float4*>(&W[(size_t)(kt + k) * 256 + n]);
            unsigned long long w0 = pack2(w.x, w.x), w1 = pack2(w.y, w.y);
            unsigned long long w2 = pack2(w.z, w.z), w3 = pack2(w.w, w.w);
#pragma unroll
            for (int p = 0; p < 8; p++) {
                unsigned long long a2 =
                    *reinterpret_cast<const unsigned long long*>(&a_s[k][rb + 2 * p]);
                fma2(acc[p][0], a2, w0);
                fma2(acc[p][1], a2, w1);
                fma2(acc[p][2], a2, w2);
                fma2(acc[p][3], a2, w3);
            }
        }
    }
    float4 bv = *reinterpret_cast<const float4*>(&bias[n]);
#pragma unroll
    for (int p = 0; p < 8; p++) {
        float lo[4], hi[4];
#pragma unroll
        for (int c = 0; c < 4; c++) unpack2(acc[p][c], lo[c], hi[c]);
        int r = r0 + rb + 2 * p;
        float4 v0 = {reluf(lo[0] + bv.x), reluf(lo[1] + bv.y), reluf(lo[2] + bv.z), reluf(lo[3] + bv.w)};
        float4 v1 = {reluf(hi[0] + bv.x), reluf(hi[1] + bv.y), reluf(hi[2] + bv.z), reluf(hi[3] + bv.w)};
        *reinterpret_cast<float4*>(&Out[(size_t)r * 256 + n])       = v0;
        *reinterpret_cast<float4*>(&Out[(size_t)(r + 1) * 256 + n]) = v1;
    }
}

// ---------------- tail: d2+relu, d3+relu, BN, out, softmax ----------------
__global__ void __launch_bounds__(128) tail_kernel(
    const float* __restrict__ H1,
    const float* __restrict__ W2, const float* __restrict__ B2,
    const float* __restrict__ W3, const float* __restrict__ B3,
    const float* __restrict__ G, const float* __restrict__ Bb,
    const float* __restrict__ M, const float* __restrict__ V,
    const float* __restrict__ WO, const float* __restrict__ BO,
    float* __restrict__ Out) {
    __shared__ float h1s[4][256];
    __shared__ float h2s[4][128];
    __shared__ float h3s[4][64];
    int tid = threadIdx.x, lane = tid & 31, w = tid >> 5;
    int r0 = blockIdx.x * 4;
    for (int i = tid; i < 4 * 256; i += 128) h1s[i >> 8][i & 255] = H1[(size_t)r0 * 256 + i];
    __syncthreads();

    {
        int j = lane * 4;
        float4 bv = *reinterpret_cast<const float4*>(&B2[j]);
        float a0 = bv.x, a1 = bv.y, a2 = bv.z, a3 = bv.w;
#pragma unroll 4
        for (int k = 0; k < 256; k++) {
            float a = h1s[w][k];
            float4 wv = *reinterpret_cast<const float4*>(&W2[(size_t)k * 128 + j]);
            a0 += a * wv.x; a1 += a * wv.y; a2 += a * wv.z; a3 += a * wv.w;
        }
        h2s[w][j]     = reluf(a0);
        h2s[w][j + 1] = reluf(a1);
        h2s[w][j + 2] = reluf(a2);
        h2s[w][j + 3] = reluf(a3);
    }
    __syncwarp();
    {
        int j = lane * 2;
        float a0 = B3[j], a1 = B3[j + 1];
#pragma unroll 4
        for (int k = 0; k < 128; k++) {
            float a = h2s[w][k];
            float2 wv = *reinterpret_cast<const float2*>(&W3[(size_t)k * 64 + j]);
            a0 += a * wv.x; a1 += a * wv.y;
        }
        a0 = reluf(a0); a1 = reluf(a1);
        float s0 = rsqrtf(V[j] + 1e-3f)     * G[j];
        float s1 = rsqrtf(V[j + 1] + 1e-3f) * G[j + 1];
        h3s[w][j]     = (a0 - M[j])     * s0 + Bb[j];
        h3s[w][j + 1] = (a1 - M[j + 1]) * s1 + Bb[j + 1];
    }
    __syncwarp();
    float logit = -3.0e38f;
    if (lane < 26) {
        float a = BO[lane];
#pragma unroll 4
        for (int k = 0; k < 64; k++) a += h3s[w][k] * WO[(size_t)k * 26 + lane];
        logit = a;
    }
    float mx = logit;
#pragma unroll
    for (int o = 16; o; o >>= 1) mx = fmaxf(mx, __shfl_xor_sync(0xffffffffu, mx, o));
    float e = (lane < 26) ? __expf(logit - mx) : 0.f;
    float s = e;
#pragma unroll
    for (int o = 16; o; o >>= 1) s += __shfl_xor_sync(0xffffffffu, s, o);
    if (lane < 26) Out[(size_t)(r0 + w) * 26 + lane] = e * __fdividef(1.f, s);
}

// ---------------- launch ----------------
extern "C" void kernel_launch(void* const* d_in, const int* in_sizes, int n_in,
                              void* d_out, int out_size) {
    const float* x   = (const float*)d_in[0];
    const float* w1f = (const float*)d_in[1];
    const float* u1f = (const float*)d_in[2];
    const float* b1f = (const float*)d_in[3];
    const float* w1b = (const float*)d_in[4];
    const float* u1b = (const float*)d_in[5];
    const float* b1b = (const float*)d_in[6];
    const float* w2f = (const float*)d_in[7];
    const float* u2f = (const float*)d_in[8];
    const float* b2f = (const float*)d_in[9];
    const float* w2b = (const float*)d_in[10];
    const float* u2b = (const float*)d_in[11];
    const float* b2b = (const float*)d_in[12];
    const float* w3f = (const float*)d_in[13];
    const float* u3f = (const float*)d_in[14];
    const float* b3f = (const float*)d_in[15];
    const float* w3b = (const float*)d_in[16];
    const float* u3b = (const float*)d_in[17];
    const float* b3b = (const float*)d_in[18];
    const float* d1w = (const float*)d_in[19];
    const float* d1b = (const float*)d_in[20];
    const float* d2w = (const float*)d_in[21];
    const float* d2b = (const float*)d_in[22];
    const float* d3w = (const float*)d_in[23];
    const float* d3b = (const float*)d_in[24];
    const float* bng = (const float*)d_in[25];
    const float* bnb = (const float*)d_in[26];
    const float* bnm = (const float*)d_in[27];
    const float* bnv = (const float*)d_in[28];
    const float* ow  = (const float*)d_in[29];
    const float* ob  = (const float*)d_in[30];

    float *bufA, *bufB, *h1, *wl1, *wl2, *wl3;
    cudaGetSymbolAddress((void**)&bufA, g_bufA);
    cudaGetSymbolAddress((void**)&bufB, g_bufB);
    cudaGetSymbolAddress((void**)&h1, g_h1);
    cudaGetSymbolAddress((void**)&wl1, g_wl1);
    cudaGetSymbolAddress((void**)&wl2, g_wl2);
    cudaGetSymbolAddress((void**)&wl3, g_wl3);

    const size_t s1 = (126 + 2 * 64)  * 66 * sizeof(float);   // ~67 KB
    const size_t s2 = (128 + 2 * 128) * 66 * sizeof(float);   // ~101 KB
    const size_t s3 = (256 + 2 * 256) * 66 * sizeof(float);   // ~203 KB
    cudaFuncSetAttribute(lstm_kernel<126, 64, 256, 1>,
                         cudaFuncAttributeMaxDynamicSharedMemorySize, (int)s1);
    cudaFuncSetAttribute(lstm_kernel<128, 128, 512, 1>,
                         cudaFuncAttributeMaxDynamicSharedMemorySize, (int)s2);
    cudaFuncSetAttribute(lstm_kernel<256, 256, 512, 2>,
                         cudaFuncAttributeMaxDynamicSharedMemorySize, (int)s3);

    // 3 prep launches (0..2) -> lstm L1/L2/L3 at launch indices 3/4/5 (ncu -s 5 profiles L3)
    pack_lstm_w<<<256, 256>>>(w1f, u1f, w1b, u1b, wl1, 126, 64);
    pack_lstm_w<<<512, 256>>>(w2f, u2f, w2b, u2b, wl2, 128, 128);
    pack_lstm_w<<<1024, 256>>>(w3f, u3f, w3b, u3b, wl3, 256, 256);

    lstm_kernel<126, 64, 256, 1><<<dim3(BATCH / 64, 2), 256, s1>>>(x, bufA, wl1, b1f, b1b);
    lstm_kernel<128, 128, 512, 1><<<dim3(BATCH / 64, 2), 512, s2>>>(bufA, bufB, wl2, b2f, b2b);
    lstm_kernel<256, 256, 512, 2><<<dim3(BATCH / 64, 2), 512, s3>>>(bufB, bufA, wl3, b3f, b3b);

    dense1_kernel<<<BATCH / 64, 256>>>(bufA, d1w, d1b, h1);
    tail_kernel<<<BATCH / 4, 128>>>(h1, d2w, d2b, d3w, d3b, bng, bnb, bnm, bnv, ow, ob,
                                    (float*)d_out);
    (void)in_sizes; (void)n_in; (void)out_size;
}